// round 1
// baseline (speedup 1.0000x reference)
#include <cuda_runtime.h>
#include <math.h>

// Problem constants
#define BT  4096    // B*T rows
#define DM  1024    // model dim
#define DFFN 4096   // ffn dim
#define SEQ 2048    // T
#define NH  16      // heads
#define DH  64      // head dim

// -------- scratch (device globals: no allocation allowed) --------
__device__ float g_h [BT * DM];
__device__ float g_q [BT * DM];
__device__ float g_k [BT * DM];
__device__ float g_v [BT * DM];
__device__ float g_at[BT * DM];
__device__ float g_x1[BT * DM];
__device__ float g_h2[BT * DM];
__device__ float g_ff[BT * DFFN];

// ============================================================
// LayerNorm: y = (x - mean)/(std + eps)*scale + bias
// one block per row, 256 threads, D=1024
// ============================================================
__global__ void __launch_bounds__(256) ln_kernel(const float* __restrict__ x,
                                                 const float* __restrict__ sc,
                                                 const float* __restrict__ bi,
                                                 float* __restrict__ y) {
    const int row = blockIdx.x;
    const float* xr = x + (size_t)row * DM;
    float v[4];
    float s = 0.f, ss = 0.f;
#pragma unroll
    for (int i = 0; i < 4; i++) {
        v[i] = xr[threadIdx.x + 256 * i];
        s  += v[i];
        ss += v[i] * v[i];
    }
#pragma unroll
    for (int o = 16; o; o >>= 1) {
        s  += __shfl_xor_sync(0xffffffffu, s,  o);
        ss += __shfl_xor_sync(0xffffffffu, ss, o);
    }
    __shared__ float rs[8], rss[8];
    const int w = threadIdx.x >> 5, ln = threadIdx.x & 31;
    if (ln == 0) { rs[w] = s; rss[w] = ss; }
    __syncthreads();
    if (threadIdx.x == 0) {
        float ts = 0.f, tss = 0.f;
#pragma unroll
        for (int i = 0; i < 8; i++) { ts += rs[i]; tss += rss[i]; }
        rs[0] = ts; rss[0] = tss;
    }
    __syncthreads();
    const float mean = rs[0] * (1.f / DM);
    float var = rss[0] * (1.f / DM) - mean * mean;
    var = fmaxf(var, 0.f);
    const float inv = 1.f / (sqrtf(var) + 1e-5f);
    float* yr = y + (size_t)row * DM;
#pragma unroll
    for (int i = 0; i < 4; i++) {
        const int c = threadIdx.x + 256 * i;
        yr[c] = (v[i] - mean) * inv * sc[c] + bi[c];
    }
}

// ============================================================
// SGEMM: C[M,N] = A[M,K] @ B[K,N]  (row-major), fused epilogue
// mode bits: 1 = +bias[n], 2 = +residual[m,n], 4 = GELU(acc+bias)
// BM=BN=128, BK=16, 256 threads, 8x8 per-thread microtile
// All of M,N,K are multiples of 128 here -> no bounds checks.
// ============================================================
__global__ void __launch_bounds__(256) sgemm_kernel(
    const float* __restrict__ A, const float* __restrict__ B,
    const float* __restrict__ bias, const float* __restrict__ R,
    float* __restrict__ C, int M, int N, int K, int mode) {
    __shared__ float As[16][128];
    __shared__ float Bs[16][128];

    const int tid  = threadIdx.x;
    const int brow = blockIdx.y << 7;
    const int bcol = blockIdx.x << 7;
    const int tx = tid & 15, ty = tid >> 4;

    // load-index precompute
    const int aR0 = tid >> 2;              // 0..63
    const int aR1 = aR0 + 64;              // 64..127
    const int aC  = (tid & 3) << 2;        // 0,4,8,12
    const int bR0 = tid >> 5;              // 0..7
    const int bR1 = bR0 + 8;               // 8..15
    const int bC  = (tid & 31) << 2;       // 0..124

    const float* Ab = A + (size_t)brow * K;
    const float* Bb = B + bcol;

    float4 ar0 = *(const float4*)(Ab + (size_t)aR0 * K + aC);
    float4 ar1 = *(const float4*)(Ab + (size_t)aR1 * K + aC);
    float4 br0 = *(const float4*)(Bb + (size_t)bR0 * N + bC);
    float4 br1 = *(const float4*)(Bb + (size_t)bR1 * N + bC);

    float acc[8][8];
#pragma unroll
    for (int i = 0; i < 8; i++)
#pragma unroll
        for (int j = 0; j < 8; j++) acc[i][j] = 0.f;

    const int nk = K >> 4;
    for (int kt = 0; kt < nk; kt++) {
        // stage to shared (A transposed)
        As[aC + 0][aR0] = ar0.x; As[aC + 1][aR0] = ar0.y;
        As[aC + 2][aR0] = ar0.z; As[aC + 3][aR0] = ar0.w;
        As[aC + 0][aR1] = ar1.x; As[aC + 1][aR1] = ar1.y;
        As[aC + 2][aR1] = ar1.z; As[aC + 3][aR1] = ar1.w;
        *(float4*)&Bs[bR0][bC] = br0;
        *(float4*)&Bs[bR1][bC] = br1;
        __syncthreads();

        if (kt + 1 < nk) {               // prefetch next tile into regs
            const int ko = (kt + 1) << 4;
            ar0 = *(const float4*)(Ab + (size_t)aR0 * K + ko + aC);
            ar1 = *(const float4*)(Ab + (size_t)aR1 * K + ko + aC);
            br0 = *(const float4*)(Bb + (size_t)(ko + bR0) * N + bC);
            br1 = *(const float4*)(Bb + (size_t)(ko + bR1) * N + bC);
        }

#pragma unroll
        for (int k = 0; k < 16; k++) {
            float a[8], bv[8];
            *(float4*)(a)      = *(const float4*)&As[k][ty << 3];
            *(float4*)(a + 4)  = *(const float4*)&As[k][(ty << 3) + 4];
            *(float4*)(bv)     = *(const float4*)&Bs[k][tx << 3];
            *(float4*)(bv + 4) = *(const float4*)&Bs[k][(tx << 3) + 4];
#pragma unroll
            for (int i = 0; i < 8; i++)
#pragma unroll
                for (int j = 0; j < 8; j++)
                    acc[i][j] = fmaf(a[i], bv[j], acc[i][j]);
        }
        __syncthreads();
    }

    // epilogue
    const int row0 = brow + (ty << 3);
    const int col0 = bcol + (tx << 3);
    float bvv[8];
#pragma unroll
    for (int j = 0; j < 8; j++) bvv[j] = (mode & 1) ? bias[col0 + j] : 0.f;
#pragma unroll
    for (int i = 0; i < 8; i++) {
        const size_t off = (size_t)(row0 + i) * N + col0;
#pragma unroll
        for (int j = 0; j < 8; j++) {
            float vv = acc[i][j] + bvv[j];
            if (mode & 4) vv = 0.5f * vv * (1.f + erff(vv * 0.70710678118654752f));
            if (mode & 2) vv += R[off + j];
            C[off + j] = vv;
        }
    }
}

// ============================================================
// Causal flash attention, fp32. BQ=64, BK=32, DH=64.
// block = 128 threads, laid out 16 (rows) x 8 (cols).
// Each thread: 4 q-rows (tr+16i), 8 d-cols (tc+8j) of O,
//              4 q-rows x 4 kv-cols of S.
// ============================================================
#define BQ 64
#define BK 32

__global__ void __launch_bounds__(128) flash_kernel(
    const float* __restrict__ Q, const float* __restrict__ K,
    const float* __restrict__ V, float* __restrict__ O) {
    __shared__ float Qs [BQ][DH + 1];   // +1 pad: distinct banks per row
    __shared__ float KsT[DH][BK + 1];
    __shared__ float Vs [BK][DH + 4];   // stride 68: float4-aligned, conflict-free reads
    __shared__ float Ss [BQ][BK + 1];

    const int tid  = threadIdx.x;
    const int tr   = tid >> 3;          // 0..15
    const int tc   = tid & 7;           // 0..7
    const int q0   = blockIdx.x * BQ;
    const int head = blockIdx.y;
    const int b    = blockIdx.z;
    const size_t base = ((size_t)b * SEQ) * DM + head * DH;

    // load Q tile (scaled by 1/sqrt(DH))
#pragma unroll
    for (int u = 0; u < 8; u++) {
        const int f  = tid + 128 * u;    // 0..1023 float4 index
        const int r  = f >> 4;
        const int c4 = (f & 15) << 2;
        float4 v4 = *(const float4*)&Q[base + (size_t)(q0 + r) * DM + c4];
        Qs[r][c4 + 0] = v4.x * 0.125f;
        Qs[r][c4 + 1] = v4.y * 0.125f;
        Qs[r][c4 + 2] = v4.z * 0.125f;
        Qs[r][c4 + 3] = v4.w * 0.125f;
    }

    float m_i[4], l_i[4], o[4][8];
#pragma unroll
    for (int i = 0; i < 4; i++) {
        m_i[i] = -1e30f; l_i[i] = 0.f;
#pragma unroll
        for (int j = 0; j < 8; j++) o[i][j] = 0.f;
    }

    const int kv_end = q0 + BQ;          // causal: no tiles past the diagonal block
    for (int kv0 = 0; kv0 < kv_end; kv0 += BK) {
        __syncthreads();                 // prior tile fully consumed
        // load K (transposed) and V tiles
#pragma unroll
        for (int u = 0; u < 4; u++) {
            const int f  = tid + 128 * u;  // 0..511
            const int r  = f >> 4;
            const int c4 = (f & 15) << 2;
            float4 kk = *(const float4*)&K[base + (size_t)(kv0 + r) * DM + c4];
            KsT[c4 + 0][r] = kk.x; KsT[c4 + 1][r] = kk.y;
            KsT[c4 + 2][r] = kk.z; KsT[c4 + 3][r] = kk.w;
            float4 vv = *(const float4*)&V[base + (size_t)(kv0 + r) * DM + c4];
            *(float4*)&Vs[r][c4] = vv;
        }
        __syncthreads();

        // S = Q K^T (scaled)
        float s[4][4];
#pragma unroll
        for (int i = 0; i < 4; i++)
#pragma unroll
            for (int j = 0; j < 4; j++) s[i][j] = 0.f;
#pragma unroll 4
        for (int d = 0; d < DH; d++) {
            float qv[4], kw[4];
#pragma unroll
            for (int i = 0; i < 4; i++) qv[i] = Qs[tr + 16 * i][d];
#pragma unroll
            for (int j = 0; j < 4; j++) kw[j] = KsT[d][tc + 8 * j];
#pragma unroll
            for (int i = 0; i < 4; i++)
#pragma unroll
                for (int j = 0; j < 4; j++)
                    s[i][j] = fmaf(qv[i], kw[j], s[i][j]);
        }

        // causal mask + online softmax
#pragma unroll
        for (int i = 0; i < 4; i++) {
            const int qg = q0 + tr + 16 * i;
#pragma unroll
            for (int j = 0; j < 4; j++) {
                const int kg = kv0 + tc + 8 * j;
                if (kg > qg) s[i][j] = -1e30f;
            }
            float mloc = fmaxf(fmaxf(s[i][0], s[i][1]), fmaxf(s[i][2], s[i][3]));
#pragma unroll
            for (int off = 4; off; off >>= 1)
                mloc = fmaxf(mloc, __shfl_xor_sync(0xffffffffu, mloc, off));
            const float mn = fmaxf(m_i[i], mloc);
            const float alpha = __expf(m_i[i] - mn);
            m_i[i] = mn;
            float ps = 0.f;
#pragma unroll
            for (int j = 0; j < 4; j++) {
                s[i][j] = __expf(s[i][j] - mn);
                ps += s[i][j];
            }
#pragma unroll
            for (int off = 4; off; off >>= 1)
                ps += __shfl_xor_sync(0xffffffffu, ps, off);
            l_i[i] = l_i[i] * alpha + ps;
#pragma unroll
            for (int j = 0; j < 8; j++) o[i][j] *= alpha;
#pragma unroll
            for (int j = 0; j < 4; j++)
                Ss[tr + 16 * i][tc + 8 * j] = s[i][j];
        }
        __syncthreads();

        // O += P @ V
#pragma unroll 4
        for (int kv = 0; kv < BK; kv++) {
            float pv[4], vv[8];
#pragma unroll
            for (int i = 0; i < 4; i++) pv[i] = Ss[tr + 16 * i][kv];
#pragma unroll
            for (int j = 0; j < 8; j++) vv[j] = Vs[kv][tc + 8 * j];
#pragma unroll
            for (int i = 0; i < 4; i++)
#pragma unroll
                for (int j = 0; j < 8; j++)
                    o[i][j] = fmaf(pv[i], vv[j], o[i][j]);
        }
    }

    // write out O / l
#pragma unroll
    for (int i = 0; i < 4; i++) {
        const float inv = 1.f / l_i[i];
        const size_t roff = base + (size_t)(q0 + tr + 16 * i) * DM;
#pragma unroll
        for (int j = 0; j < 8; j++)
            O[roff + tc + 8 * j] = o[i][j] * inv;
    }
}

// ============================================================
// launch
// ============================================================
extern "C" void kernel_launch(void* const* d_in, const int* in_sizes, int n_in,
                              void* d_out, int out_size) {
    const float* x    = (const float*)d_in[0];
    const float* wq   = (const float*)d_in[1];
    const float* wk   = (const float*)d_in[2];
    const float* wv   = (const float*)d_in[3];
    const float* wo   = (const float*)d_in[4];
    const float* bo   = (const float*)d_in[5];
    const float* w1   = (const float*)d_in[6];
    const float* b1   = (const float*)d_in[7];
    const float* w2   = (const float*)d_in[8];
    const float* b2   = (const float*)d_in[9];
    const float* ln1s = (const float*)d_in[10];
    const float* ln1b = (const float*)d_in[11];
    const float* ln2s = (const float*)d_in[12];
    const float* ln2b = (const float*)d_in[13];
    float* out = (float*)d_out;

    float *h, *q, *k, *v, *at, *x1, *h2, *ff;
    cudaGetSymbolAddress((void**)&h,  g_h);
    cudaGetSymbolAddress((void**)&q,  g_q);
    cudaGetSymbolAddress((void**)&k,  g_k);
    cudaGetSymbolAddress((void**)&v,  g_v);
    cudaGetSymbolAddress((void**)&at, g_at);
    cudaGetSymbolAddress((void**)&x1, g_x1);
    cudaGetSymbolAddress((void**)&h2, g_h2);
    cudaGetSymbolAddress((void**)&ff, g_ff);

    const dim3 gD (DM   / 128, BT / 128);   // N=1024 GEMMs
    const dim3 gF (DFFN / 128, BT / 128);   // N=4096 GEMM
    const dim3 gAt(SEQ / BQ, NH, 2);

    // 1) LN1
    ln_kernel<<<BT, 256>>>(x, ln1s, ln1b, h);
    // 2) Q,K,V projections
    sgemm_kernel<<<gD, 256>>>(h, wq, nullptr, nullptr, q, BT, DM, DM, 0);
    sgemm_kernel<<<gD, 256>>>(h, wk, nullptr, nullptr, k, BT, DM, DM, 0);
    sgemm_kernel<<<gD, 256>>>(h, wv, nullptr, nullptr, v, BT, DM, DM, 0);
    // 3) causal flash attention
    flash_kernel<<<gAt, 128>>>(q, k, v, at);
    // 4) out-proj + bias + residual
    sgemm_kernel<<<gD, 256>>>(at, wo, bo, x, x1, BT, DM, DM, 1 | 2);
    // 5) LN2
    ln_kernel<<<BT, 256>>>(x1, ln2s, ln2b, h2);
    // 6) FFN1 + bias + GELU
    sgemm_kernel<<<gF, 256>>>(h2, w1, b1, nullptr, ff, BT, DFFN, DM, 1 | 4);
    // 7) FFN2 + bias + residual -> out
    sgemm_kernel<<<gD, 256>>>(ff, w2, b2, x1, out, BT, DM, DFFN, 1 | 2);
}

// round 3
// speedup vs baseline: 1.9823x; 1.9823x over previous
#include <cuda_runtime.h>
#include <cuda_bf16.h>
#include <math.h>
#include <stdint.h>

// Problem constants
#define BT   4096
#define DM   1024
#define DFFN 4096
#define SEQ  2048
#define NH   16
#define DH   64

// ---------------- scratch (device globals) ----------------
__device__ float g_q [BT * DM];
__device__ float g_k [BT * DM];
__device__ float g_v [BT * DM];
__device__ float g_x1[BT * DM];
__device__ __nv_bfloat16 g_hhi [BT * DM],   g_hlo [BT * DM];
__device__ __nv_bfloat16 g_athi[BT * DM],   g_atlo[BT * DM];
__device__ __nv_bfloat16 g_h2hi[BT * DM],   g_h2lo[BT * DM];
__device__ __nv_bfloat16 g_ffhi[BT * DFFN], g_fflo[BT * DFFN];
__device__ __nv_bfloat16 g_wqh[DM * DM],    g_wql[DM * DM];
__device__ __nv_bfloat16 g_wkh[DM * DM],    g_wkl[DM * DM];
__device__ __nv_bfloat16 g_wvh[DM * DM],    g_wvl[DM * DM];
__device__ __nv_bfloat16 g_woh[DM * DM],    g_wol[DM * DM];
__device__ __nv_bfloat16 g_w1h[DFFN * DM],  g_w1l[DFFN * DM];   // [N=4096,K=1024]
__device__ __nv_bfloat16 g_w2h[DM * DFFN],  g_w2l[DM * DFFN];   // [N=1024,K=4096]

// ---------------- PTX helpers (base sm_80+ PTX only) ----------------
__device__ __forceinline__ uint32_t smem_u32(const void* p) {
    return (uint32_t)__cvta_generic_to_shared(p);
}
__device__ __forceinline__ void cp16(uint32_t dst, const void* src) {
    asm volatile("cp.async.cg.shared.global [%0], [%1], 16;" :: "r"(dst), "l"(src));
}
__device__ __forceinline__ void ldsm4(uint32_t* r, uint32_t addr) {
    asm volatile("ldmatrix.sync.aligned.m8n8.x4.shared.b16 {%0,%1,%2,%3}, [%4];"
                 : "=r"(r[0]), "=r"(r[1]), "=r"(r[2]), "=r"(r[3]) : "r"(addr));
}
__device__ __forceinline__ void mma16816(float* d, const uint32_t* a, const uint32_t* b) {
    asm volatile("mma.sync.aligned.m16n8k16.row.col.f32.bf16.bf16.f32 "
                 "{%0,%1,%2,%3}, {%4,%5,%6,%7}, {%8,%9}, {%0,%1,%2,%3};"
                 : "+f"(d[0]), "+f"(d[1]), "+f"(d[2]), "+f"(d[3])
                 : "r"(a[0]), "r"(a[1]), "r"(a[2]), "r"(a[3]), "r"(b[0]), "r"(b[1]));
}

// ============================================================
// LayerNorm -> bf16 hi/lo split output
// ============================================================
__global__ void __launch_bounds__(256) ln_kernel(const float* __restrict__ x,
                                                 const float* __restrict__ sc,
                                                 const float* __restrict__ bi,
                                                 __nv_bfloat16* __restrict__ yhi,
                                                 __nv_bfloat16* __restrict__ ylo) {
    const int row = blockIdx.x;
    const float* xr = x + (size_t)row * DM;
    float v[4];
    float s = 0.f, ss = 0.f;
#pragma unroll
    for (int i = 0; i < 4; i++) {
        v[i] = xr[threadIdx.x + 256 * i];
        s += v[i]; ss += v[i] * v[i];
    }
#pragma unroll
    for (int o = 16; o; o >>= 1) {
        s  += __shfl_xor_sync(0xffffffffu, s,  o);
        ss += __shfl_xor_sync(0xffffffffu, ss, o);
    }
    __shared__ float rs[8], rss[8];
    const int w = threadIdx.x >> 5, ln = threadIdx.x & 31;
    if (ln == 0) { rs[w] = s; rss[w] = ss; }
    __syncthreads();
    if (threadIdx.x == 0) {
        float ts = 0.f, tss = 0.f;
#pragma unroll
        for (int i = 0; i < 8; i++) { ts += rs[i]; tss += rss[i]; }
        rs[0] = ts; rss[0] = tss;
    }
    __syncthreads();
    const float mean = rs[0] * (1.f / DM);
    float var = rss[0] * (1.f / DM) - mean * mean;
    var = fmaxf(var, 0.f);
    const float inv = 1.f / (sqrtf(var) + 1e-5f);
#pragma unroll
    for (int i = 0; i < 4; i++) {
        const int c = threadIdx.x + 256 * i;
        const float y = (v[i] - mean) * inv * sc[c] + bi[c];
        const __nv_bfloat16 h = __float2bfloat16(y);
        yhi[(size_t)row * DM + c] = h;
        ylo[(size_t)row * DM + c] = __float2bfloat16(y - __bfloat162float(h));
    }
}

// ============================================================
// Weight transpose + bf16 hi/lo split: W[K,N] fp32 -> Whi/Wlo[N,K] bf16
// ============================================================
__global__ void __launch_bounds__(256) wsplit_kernel(const float* __restrict__ W,
                                                     __nv_bfloat16* __restrict__ Whi,
                                                     __nv_bfloat16* __restrict__ Wlo,
                                                     int K, int N) {
    __shared__ float t[32][33];
    const int n0 = blockIdx.x << 5, k0 = blockIdx.y << 5;
    const int tx = threadIdx.x & 31, ty = threadIdx.x >> 5;
#pragma unroll
    for (int i = 0; i < 4; i++)
        t[ty + 8 * i][tx] = W[(size_t)(k0 + ty + 8 * i) * N + n0 + tx];
    __syncthreads();
#pragma unroll
    for (int i = 0; i < 4; i++) {
        const float vv = t[tx][ty + 8 * i];
        const __nv_bfloat16 h = __float2bfloat16(vv);
        const size_t o = (size_t)(n0 + ty + 8 * i) * K + k0 + tx;
        Whi[o] = h;
        Wlo[o] = __float2bfloat16(vv - __bfloat162float(h));
    }
}

// ============================================================
// HMMA (mma.sync) bf16 split GEMM:
//   C[M, N] = (Ahi+Alo)[M,K] @ (Bhi+Blo)[N,K]^T   (3-term split)
// BM=BN=128, BK=64, 256 threads = 8 warps (2 M x 4 N), warp tile 64x32.
// 2-stage cp.async pipeline. Padded smem rows (144B) -> conflict-free LDSM.
// mode bits: 1=+bias, 2=+residual, 4=GELU. Cf!=null -> fp32 out,
// else bf16 hi/lo split out.
// ============================================================
#define RSTRIDE 144                    // 64 halves data + 8 halves pad
#define MATB    (128 * RSTRIDE)        // 18432 B per matrix tile
#define STAGEB  (4 * MATB)             // Ahi,Alo,Bhi,Blo

__global__ void __launch_bounds__(256, 1) hgemm_kernel(
    const __nv_bfloat16* __restrict__ Ahi, const __nv_bfloat16* __restrict__ Alo,
    const __nv_bfloat16* __restrict__ Bhi, const __nv_bfloat16* __restrict__ Blo,
    const float* __restrict__ bias, const float* __restrict__ Rres,
    float* __restrict__ Cf, __nv_bfloat16* __restrict__ Chi, __nv_bfloat16* __restrict__ Clo,
    int N, int K, int mode) {
    extern __shared__ char dsm[];
    const uint32_t sb = smem_u32(dsm);

    const int tid  = threadIdx.x;
    const int lane = tid & 31;
    const int wid  = tid >> 5;
    const int wm   = wid & 1;          // 2 M groups of 64
    const int wn   = wid >> 1;         // 4 N groups of 32
    const int brow = blockIdx.y << 7;
    const int bcol = blockIdx.x << 7;

    auto load_stage = [&](int c, int s) {
        const uint32_t st = sb + s * STAGEB;
        const size_t kb = (size_t)c << 6;
#pragma unroll
        for (int i = 0; i < 4; i++) {
            const int idx = tid + (i << 8);       // 0..1023
            const int r  = idx >> 3;
            const int ch = idx & 7;
            const uint32_t d = st + r * RSTRIDE + (ch << 4);
            const size_t ael = (size_t)(brow + r) * K + kb + (ch << 3);
            const size_t bel = (size_t)(bcol + r) * K + kb + (ch << 3);
            cp16(d,            Ahi + ael);
            cp16(d +     MATB, Alo + ael);
            cp16(d + 2 * MATB, Bhi + bel);
            cp16(d + 3 * MATB, Blo + bel);
        }
        asm volatile("cp.async.commit_group;" ::: "memory");
    };

    float acc[4][4][4];
#pragma unroll
    for (int mt = 0; mt < 4; mt++)
#pragma unroll
        for (int nt = 0; nt < 4; nt++)
#pragma unroll
            for (int e = 0; e < 4; e++) acc[mt][nt][e] = 0.f;

    load_stage(0, 0);

    const int NC = K >> 6;
    for (int c = 0; c < NC; c++) {
        const int s = c & 1;
        asm volatile("cp.async.wait_group 0;" ::: "memory");
        __syncthreads();
        if (c + 1 < NC) load_stage(c + 1, s ^ 1);

        const uint32_t st = sb + s * STAGEB;
#pragma unroll
        for (int kk = 0; kk < 4; kk++) {
            uint32_t Ah[4][4], Al[4][4], Bh[2][4], Bl[2][4];
#pragma unroll
            for (int mt = 0; mt < 4; mt++) {
                const int row  = (wm << 6) + (mt << 4) + (lane & 7) + (((lane >> 3) & 1) << 3);
                const int colh = (kk << 4) + ((lane >> 4) << 3);
                const uint32_t ad = st + row * RSTRIDE + (colh << 1);
                ldsm4(Ah[mt], ad);
                ldsm4(Al[mt], ad + MATB);
            }
#pragma unroll
            for (int p = 0; p < 2; p++) {
                const int row  = (wn << 5) + (p << 4) + (lane & 7) + ((lane >= 16) << 3);
                const int colh = (kk << 4) + (((lane >> 3) & 1) << 3);
                const uint32_t bd = st + 2 * MATB + row * RSTRIDE + (colh << 1);
                ldsm4(Bh[p], bd);
                ldsm4(Bl[p], bd + MATB);
            }
#pragma unroll
            for (int mt = 0; mt < 4; mt++)
#pragma unroll
                for (int nt = 0; nt < 4; nt++) {
                    const uint32_t* bh = &Bh[nt >> 1][(nt & 1) << 1];
                    const uint32_t* bl = &Bl[nt >> 1][(nt & 1) << 1];
                    mma16816(acc[mt][nt], Ah[mt], bh);
                    mma16816(acc[mt][nt], Ah[mt], bl);
                    mma16816(acc[mt][nt], Al[mt], bh);
                }
        }
        __syncthreads();
    }

    // ---------------- epilogue (direct from registers) ----------------
    const int lr = lane >> 2;
    const int lc = (lane & 3) << 1;
#pragma unroll
    for (int mt = 0; mt < 4; mt++) {
#pragma unroll
        for (int h = 0; h < 2; h++) {
            const int row = brow + (wm << 6) + (mt << 4) + lr + (h << 3);
            const size_t crow = (size_t)row * N;
#pragma unroll
            for (int nt = 0; nt < 4; nt++) {
                const int col = bcol + (wn << 5) + (nt << 3) + lc;
                float v0 = acc[mt][nt][2 * h];
                float v1 = acc[mt][nt][2 * h + 1];
                if (mode & 1) {
                    const float2 bb = *(const float2*)&bias[col];
                    v0 += bb.x; v1 += bb.y;
                }
                if (mode & 4) {
                    v0 = 0.5f * v0 * (1.f + erff(v0 * 0.70710678118654752f));
                    v1 = 0.5f * v1 * (1.f + erff(v1 * 0.70710678118654752f));
                }
                if (mode & 2) {
                    const float2 rr = *(const float2*)&Rres[crow + col];
                    v0 += rr.x; v1 += rr.y;
                }
                if (Cf) {
                    float2 o; o.x = v0; o.y = v1;
                    *(float2*)&Cf[crow + col] = o;
                } else {
                    const __nv_bfloat16 h0 = __float2bfloat16(v0);
                    const __nv_bfloat16 h1 = __float2bfloat16(v1);
                    *(__nv_bfloat162*)&Chi[crow + col] = __nv_bfloat162(h0, h1);
                    const __nv_bfloat16 l0 = __float2bfloat16(v0 - __bfloat162float(h0));
                    const __nv_bfloat16 l1 = __float2bfloat16(v1 - __bfloat162float(h1));
                    *(__nv_bfloat162*)&Clo[crow + col] = __nv_bfloat162(l0, l1);
                }
            }
        }
    }
}

// ============================================================
// Causal flash attention, fp32, bf16 hi/lo split output
// ============================================================
#define BQ 64
#define BK 32

__global__ void __launch_bounds__(128) flash_kernel(
    const float* __restrict__ Q, const float* __restrict__ K,
    const float* __restrict__ V,
    __nv_bfloat16* __restrict__ Ohi, __nv_bfloat16* __restrict__ Olo) {
    __shared__ float Qs [BQ][DH + 1];
    __shared__ float KsT[DH][BK + 1];
    __shared__ float Vs [BK][DH + 4];
    __shared__ float Ss [BQ][BK + 1];

    const int tid  = threadIdx.x;
    const int tr   = tid >> 3;
    const int tc   = tid & 7;
    const int q0   = blockIdx.x * BQ;
    const int head = blockIdx.y;
    const int b    = blockIdx.z;
    const size_t base = ((size_t)b * SEQ) * DM + head * DH;

#pragma unroll
    for (int u = 0; u < 8; u++) {
        const int f  = tid + 128 * u;
        const int r  = f >> 4;
        const int c4 = (f & 15) << 2;
        float4 v4 = *(const float4*)&Q[base + (size_t)(q0 + r) * DM + c4];
        Qs[r][c4 + 0] = v4.x * 0.125f;
        Qs[r][c4 + 1] = v4.y * 0.125f;
        Qs[r][c4 + 2] = v4.z * 0.125f;
        Qs[r][c4 + 3] = v4.w * 0.125f;
    }

    float m_i[4], l_i[4], o[4][8];
#pragma unroll
    for (int i = 0; i < 4; i++) {
        m_i[i] = -1e30f; l_i[i] = 0.f;
#pragma unroll
        for (int j = 0; j < 8; j++) o[i][j] = 0.f;
    }

    const int kv_end = q0 + BQ;
    for (int kv0 = 0; kv0 < kv_end; kv0 += BK) {
        __syncthreads();
#pragma unroll
        for (int u = 0; u < 4; u++) {
            const int f  = tid + 128 * u;
            const int r  = f >> 4;
            const int c4 = (f & 15) << 2;
            float4 kk = *(const float4*)&K[base + (size_t)(kv0 + r) * DM + c4];
            KsT[c4 + 0][r] = kk.x; KsT[c4 + 1][r] = kk.y;
            KsT[c4 + 2][r] = kk.z; KsT[c4 + 3][r] = kk.w;
            float4 vv = *(const float4*)&V[base + (size_t)(kv0 + r) * DM + c4];
            *(float4*)&Vs[r][c4] = vv;
        }
        __syncthreads();

        float s[4][4];
#pragma unroll
        for (int i = 0; i < 4; i++)
#pragma unroll
            for (int j = 0; j < 4; j++) s[i][j] = 0.f;
#pragma unroll 4
        for (int d = 0; d < DH; d++) {
            float qv[4], kw[4];
#pragma unroll
            for (int i = 0; i < 4; i++) qv[i] = Qs[tr + 16 * i][d];
#pragma unroll
            for (int j = 0; j < 4; j++) kw[j] = KsT[d][tc + 8 * j];
#pragma unroll
            for (int i = 0; i < 4; i++)
#pragma unroll
                for (int j = 0; j < 4; j++)
                    s[i][j] = fmaf(qv[i], kw[j], s[i][j]);
        }

#pragma unroll
        for (int i = 0; i < 4; i++) {
            const int qg = q0 + tr + 16 * i;
#pragma unroll
            for (int j = 0; j < 4; j++) {
                const int kg = kv0 + tc + 8 * j;
                if (kg > qg) s[i][j] = -1e30f;
            }
            float mloc = fmaxf(fmaxf(s[i][0], s[i][1]), fmaxf(s[i][2], s[i][3]));
#pragma unroll
            for (int off = 4; off; off >>= 1)
                mloc = fmaxf(mloc, __shfl_xor_sync(0xffffffffu, mloc, off));
            const float mn = fmaxf(m_i[i], mloc);
            const float alpha = __expf(m_i[i] - mn);
            m_i[i] = mn;
            float ps = 0.f;
#pragma unroll
            for (int j = 0; j < 4; j++) {
                s[i][j] = __expf(s[i][j] - mn);
                ps += s[i][j];
            }
#pragma unroll
            for (int off = 4; off; off >>= 1)
                ps += __shfl_xor_sync(0xffffffffu, ps, off);
            l_i[i] = l_i[i] * alpha + ps;
#pragma unroll
            for (int j = 0; j < 8; j++) o[i][j] *= alpha;
#pragma unroll
            for (int j = 0; j < 4; j++)
                Ss[tr + 16 * i][tc + 8 * j] = s[i][j];
        }
        __syncthreads();

#pragma unroll 4
        for (int kv = 0; kv < BK; kv++) {
            float pv[4], vv[8];
#pragma unroll
            for (int i = 0; i < 4; i++) pv[i] = Ss[tr + 16 * i][kv];
#pragma unroll
            for (int j = 0; j < 8; j++) vv[j] = Vs[kv][tc + 8 * j];
#pragma unroll
            for (int i = 0; i < 4; i++)
#pragma unroll
                for (int j = 0; j < 8; j++)
                    o[i][j] = fmaf(pv[i], vv[j], o[i][j]);
        }
    }

#pragma unroll
    for (int i = 0; i < 4; i++) {
        const float inv = 1.f / l_i[i];
        const size_t roff = base + (size_t)(q0 + tr + 16 * i) * DM;
#pragma unroll
        for (int j = 0; j < 8; j++) {
            const float val = o[i][j] * inv;
            const __nv_bfloat16 h = __float2bfloat16(val);
            Ohi[roff + tc + 8 * j] = h;
            Olo[roff + tc + 8 * j] = __float2bfloat16(val - __bfloat162float(h));
        }
    }
}

// ============================================================
// launch
// ============================================================
extern "C" void kernel_launch(void* const* d_in, const int* in_sizes, int n_in,
                              void* d_out, int out_size) {
    const float* x    = (const float*)d_in[0];
    const float* wq   = (const float*)d_in[1];
    const float* wk   = (const float*)d_in[2];
    const float* wv   = (const float*)d_in[3];
    const float* wo   = (const float*)d_in[4];
    const float* bo   = (const float*)d_in[5];
    const float* w1   = (const float*)d_in[6];
    const float* b1   = (const float*)d_in[7];
    const float* w2   = (const float*)d_in[8];
    const float* b2   = (const float*)d_in[9];
    const float* ln1s = (const float*)d_in[10];
    const float* ln1b = (const float*)d_in[11];
    const float* ln2s = (const float*)d_in[12];
    const float* ln2b = (const float*)d_in[13];
    float* out = (float*)d_out;

    float *q, *k, *v, *x1;
    __nv_bfloat16 *hhi, *hlo, *athi, *atlo, *h2hi, *h2lo, *ffhi, *fflo;
    __nv_bfloat16 *wqh, *wql, *wkh, *wkl, *wvh, *wvl, *woh, *wol, *w1h, *w1l, *w2h, *w2l;
    cudaGetSymbolAddress((void**)&q,    g_q);
    cudaGetSymbolAddress((void**)&k,    g_k);
    cudaGetSymbolAddress((void**)&v,    g_v);
    cudaGetSymbolAddress((void**)&x1,   g_x1);
    cudaGetSymbolAddress((void**)&hhi,  g_hhi);  cudaGetSymbolAddress((void**)&hlo,  g_hlo);
    cudaGetSymbolAddress((void**)&athi, g_athi); cudaGetSymbolAddress((void**)&atlo, g_atlo);
    cudaGetSymbolAddress((void**)&h2hi, g_h2hi); cudaGetSymbolAddress((void**)&h2lo, g_h2lo);
    cudaGetSymbolAddress((void**)&ffhi, g_ffhi); cudaGetSymbolAddress((void**)&fflo, g_fflo);
    cudaGetSymbolAddress((void**)&wqh,  g_wqh);  cudaGetSymbolAddress((void**)&wql,  g_wql);
    cudaGetSymbolAddress((void**)&wkh,  g_wkh);  cudaGetSymbolAddress((void**)&wkl,  g_wkl);
    cudaGetSymbolAddress((void**)&wvh,  g_wvh);  cudaGetSymbolAddress((void**)&wvl,  g_wvl);
    cudaGetSymbolAddress((void**)&woh,  g_woh);  cudaGetSymbolAddress((void**)&wol,  g_wol);
    cudaGetSymbolAddress((void**)&w1h,  g_w1h);  cudaGetSymbolAddress((void**)&w1l,  g_w1l);
    cudaGetSymbolAddress((void**)&w2h,  g_w2h);  cudaGetSymbolAddress((void**)&w2l,  g_w2l);

    const int SMEM = 2 * STAGEB;   // 147456 bytes
    cudaFuncSetAttribute(hgemm_kernel, cudaFuncAttributeMaxDynamicSharedMemorySize, SMEM);

    const dim3 gW1(DM / 32, DM / 32);
    const dim3 gWF1(DFFN / 32, DM / 32);
    const dim3 gWF2(DM / 32, DFFN / 32);

    // weight transpose + split
    wsplit_kernel<<<gW1, 256>>>(wq, wqh, wql, DM, DM);
    wsplit_kernel<<<gW1, 256>>>(wk, wkh, wkl, DM, DM);
    wsplit_kernel<<<gW1, 256>>>(wv, wvh, wvl, DM, DM);
    wsplit_kernel<<<gW1, 256>>>(wo, woh, wol, DM, DM);
    wsplit_kernel<<<gWF1, 256>>>(w1, w1h, w1l, DM, DFFN);
    wsplit_kernel<<<gWF2, 256>>>(w2, w2h, w2l, DFFN, DM);

    // LN1 -> h (bf16 split)
    ln_kernel<<<BT, 256>>>(x, ln1s, ln1b, hhi, hlo);

    const dim3 gD(DM / 128, BT / 128);     // (8, 32)
    const dim3 gF(DFFN / 128, BT / 128);   // (32, 32)
    const dim3 gAt(SEQ / BQ, NH, 2);

    // QKV projections (fp32 out for flash)
    hgemm_kernel<<<gD, 256, SMEM>>>(hhi, hlo, wqh, wql, nullptr, nullptr,
                                    q, nullptr, nullptr, DM, DM, 0);
    hgemm_kernel<<<gD, 256, SMEM>>>(hhi, hlo, wkh, wkl, nullptr, nullptr,
                                    k, nullptr, nullptr, DM, DM, 0);
    hgemm_kernel<<<gD, 256, SMEM>>>(hhi, hlo, wvh, wvl, nullptr, nullptr,
                                    v, nullptr, nullptr, DM, DM, 0);
    // attention (bf16 split out)
    flash_kernel<<<gAt, 128>>>(q, k, v, athi, atlo);
    // out-proj + bias + residual -> x1 (fp32)
    hgemm_kernel<<<gD, 256, SMEM>>>(athi, atlo, woh, wol, bo, x,
                                    x1, nullptr, nullptr, DM, DM, 1 | 2);
    // LN2 -> h2 (bf16 split)
    ln_kernel<<<BT, 256>>>(x1, ln2s, ln2b, h2hi, h2lo);
    // FFN1 + bias + GELU -> ff (bf16 split)
    hgemm_kernel<<<gF, 256, SMEM>>>(h2hi, h2lo, w1h, w1l, b1, nullptr,
                                    nullptr, ffhi, fflo, DFFN, DM, 1 | 4);
    // FFN2 + bias + residual -> out (fp32)
    hgemm_kernel<<<gD, 256, SMEM>>>(ffhi, fflo, w2h, w2l, b2, x1,
                                    out, nullptr, nullptr, DM, DFFN, 1 | 2);
}

// round 4
// speedup vs baseline: 4.6917x; 2.3668x over previous
#include <cuda_runtime.h>
#include <cuda_fp16.h>
#include <math.h>
#include <stdint.h>

// Problem constants
#define BT   4096
#define DM   1024
#define DFFN 4096
#define SEQ  2048
#define NH   16
#define DH   64

// ---------------- scratch (device globals) ----------------
__device__ __half g_h  [BT * DM];
__device__ __half g_qkv[BT * 3 * DM];
__device__ __half g_at [BT * DM];
__device__ float  g_x1 [BT * DM];
__device__ __half g_h2 [BT * DM];
__device__ __half g_ff [BT * DFFN];
__device__ __half g_wqkvh[3 * DM * DM], g_wqkvl[3 * DM * DM];  // [3072,1024]
__device__ __half g_woh[DM * DM],       g_wol[DM * DM];
__device__ __half g_w1h[DFFN * DM],     g_w1l[DFFN * DM];      // [4096,1024]
__device__ __half g_w2h[DM * DFFN],     g_w2l[DM * DFFN];      // [1024,4096]

// ---------------- PTX helpers (base sm_80+ PTX only) ----------------
__device__ __forceinline__ uint32_t smem_u32(const void* p) {
    return (uint32_t)__cvta_generic_to_shared(p);
}
__device__ __forceinline__ void cp16(uint32_t dst, const void* src) {
    asm volatile("cp.async.cg.shared.global [%0], [%1], 16;" :: "r"(dst), "l"(src));
}
__device__ __forceinline__ void ldsm4(uint32_t* r, uint32_t addr) {
    asm volatile("ldmatrix.sync.aligned.m8n8.x4.shared.b16 {%0,%1,%2,%3}, [%4];"
                 : "=r"(r[0]), "=r"(r[1]), "=r"(r[2]), "=r"(r[3]) : "r"(addr));
}
__device__ __forceinline__ void ldsm4t(uint32_t* r, uint32_t addr) {
    asm volatile("ldmatrix.sync.aligned.m8n8.x4.trans.shared.b16 {%0,%1,%2,%3}, [%4];"
                 : "=r"(r[0]), "=r"(r[1]), "=r"(r[2]), "=r"(r[3]) : "r"(addr));
}
__device__ __forceinline__ void mma16816(float* d, const uint32_t* a, const uint32_t* b) {
    asm volatile("mma.sync.aligned.m16n8k16.row.col.f32.f16.f16.f32 "
                 "{%0,%1,%2,%3}, {%4,%5,%6,%7}, {%8,%9}, {%0,%1,%2,%3};"
                 : "+f"(d[0]), "+f"(d[1]), "+f"(d[2]), "+f"(d[3])
                 : "r"(a[0]), "r"(a[1]), "r"(a[2]), "r"(a[3]), "r"(b[0]), "r"(b[1]));
}
__device__ __forceinline__ float ex2(float x) {
    float y;
    asm("ex2.approx.f32 %0, %1;" : "=f"(y) : "f"(x));
    return y;
}

// ============================================================
// LayerNorm -> fp16 output
// ============================================================
__global__ void __launch_bounds__(256) ln_kernel(const float* __restrict__ x,
                                                 const float* __restrict__ sc,
                                                 const float* __restrict__ bi,
                                                 __half* __restrict__ y) {
    const int row = blockIdx.x;
    const float* xr = x + (size_t)row * DM;
    float v[4];
    float s = 0.f, ss = 0.f;
#pragma unroll
    for (int i = 0; i < 4; i++) {
        v[i] = xr[threadIdx.x + 256 * i];
        s += v[i]; ss += v[i] * v[i];
    }
#pragma unroll
    for (int o = 16; o; o >>= 1) {
        s  += __shfl_xor_sync(0xffffffffu, s,  o);
        ss += __shfl_xor_sync(0xffffffffu, ss, o);
    }
    __shared__ float rs[8], rss[8];
    const int w = threadIdx.x >> 5, ln = threadIdx.x & 31;
    if (ln == 0) { rs[w] = s; rss[w] = ss; }
    __syncthreads();
    if (threadIdx.x == 0) {
        float ts = 0.f, tss = 0.f;
#pragma unroll
        for (int i = 0; i < 8; i++) { ts += rs[i]; tss += rss[i]; }
        rs[0] = ts; rss[0] = tss;
    }
    __syncthreads();
    const float mean = rs[0] * (1.f / DM);
    float var = rss[0] * (1.f / DM) - mean * mean;
    var = fmaxf(var, 0.f);
    const float inv = 1.f / (sqrtf(var) + 1e-5f);
#pragma unroll
    for (int i = 0; i < 4; i++) {
        const int c = threadIdx.x + 256 * i;
        y[(size_t)row * DM + c] = __float2half((v[i] - mean) * inv * sc[c] + bi[c]);
    }
}

// ============================================================
// Weight transpose + fp16 hi/lo split: W[K,N] fp32 -> Whi/Wlo[N,K] fp16
// ============================================================
__global__ void __launch_bounds__(256) wsplit_kernel(const float* __restrict__ W,
                                                     __half* __restrict__ Whi,
                                                     __half* __restrict__ Wlo,
                                                     int K, int N) {
    __shared__ float t[32][33];
    const int n0 = blockIdx.x << 5, k0 = blockIdx.y << 5;
    const int tx = threadIdx.x & 31, ty = threadIdx.x >> 5;
#pragma unroll
    for (int i = 0; i < 4; i++)
        t[ty + 8 * i][tx] = W[(size_t)(k0 + ty + 8 * i) * N + n0 + tx];
    __syncthreads();
#pragma unroll
    for (int i = 0; i < 4; i++) {
        const float vv = t[tx][ty + 8 * i];
        const __half h = __float2half(vv);
        const size_t o = (size_t)(n0 + ty + 8 * i) * K + k0 + tx;
        Whi[o] = h;
        Wlo[o] = __float2half(vv - __half2float(h));
    }
}

// ============================================================
// HMMA fp16 GEMM with split weights:
//   C[M, N] = A[M,K] @ (Bh + Bl)[N,K]^T   (2 MMA terms)
// BM=BN=128, BK=64, 256 threads = 8 warps (2 M x 4 N), warp tile 64x32.
// 2-stage cp.async pipeline. 144B padded smem rows -> conflict-free LDSM.
// mode bits: 1=+bias, 2=+residual, 4=GELU. Cf!=null -> fp32 out, else fp16.
// ============================================================
#define RSTRIDE 144                    // bytes per smem row (64 halves + pad)
#define MATB    (128 * RSTRIDE)        // 18432 B per matrix tile
#define STAGEB  (3 * MATB)             // A, Bh, Bl

__global__ void __launch_bounds__(256) hgemm_kernel(
    const __half* __restrict__ A,
    const __half* __restrict__ Bh, const __half* __restrict__ Bl,
    const float* __restrict__ bias, const float* __restrict__ Rres,
    float* __restrict__ Cf, __half* __restrict__ Ch,
    int N, int K, int mode) {
    extern __shared__ char dsm[];
    const uint32_t sb = smem_u32(dsm);

    const int tid  = threadIdx.x;
    const int lane = tid & 31;
    const int wid  = tid >> 5;
    const int wm   = wid & 1;
    const int wn   = wid >> 1;
    const int brow = blockIdx.y << 7;
    const int bcol = blockIdx.x << 7;

    auto load_stage = [&](int c, int s) {
        const uint32_t st = sb + s * STAGEB;
        const size_t kb = (size_t)c << 6;
#pragma unroll
        for (int i = 0; i < 4; i++) {
            const int idx = tid + (i << 8);
            const int r  = idx >> 3;
            const int ch = idx & 7;
            const uint32_t d = st + r * RSTRIDE + (ch << 4);
            const size_t ael = (size_t)(brow + r) * K + kb + (ch << 3);
            const size_t bel = (size_t)(bcol + r) * K + kb + (ch << 3);
            cp16(d,            A  + ael);
            cp16(d +     MATB, Bh + bel);
            cp16(d + 2 * MATB, Bl + bel);
        }
        asm volatile("cp.async.commit_group;" ::: "memory");
    };

    float acc[4][4][4];
#pragma unroll
    for (int mt = 0; mt < 4; mt++)
#pragma unroll
        for (int nt = 0; nt < 4; nt++)
#pragma unroll
            for (int e = 0; e < 4; e++) acc[mt][nt][e] = 0.f;

    load_stage(0, 0);

    const int NC = K >> 6;
    for (int c = 0; c < NC; c++) {
        const int s = c & 1;
        asm volatile("cp.async.wait_group 0;" ::: "memory");
        __syncthreads();
        if (c + 1 < NC) load_stage(c + 1, s ^ 1);

        const uint32_t st = sb + s * STAGEB;
#pragma unroll
        for (int kk = 0; kk < 4; kk++) {
            uint32_t Af[4][4], Bhf[2][4], Blf[2][4];
#pragma unroll
            for (int mt = 0; mt < 4; mt++) {
                const int row  = (wm << 6) + (mt << 4) + (lane & 7) + (((lane >> 3) & 1) << 3);
                const int colh = (kk << 4) + ((lane >> 4) << 3);
                ldsm4(Af[mt], st + row * RSTRIDE + (colh << 1));
            }
#pragma unroll
            for (int p = 0; p < 2; p++) {
                const int row  = (wn << 5) + (p << 4) + (lane & 7) + ((lane >= 16) << 3);
                const int colh = (kk << 4) + (((lane >> 3) & 1) << 3);
                const uint32_t bd = st + MATB + row * RSTRIDE + (colh << 1);
                ldsm4(Bhf[p], bd);
                ldsm4(Blf[p], bd + MATB);
            }
#pragma unroll
            for (int mt = 0; mt < 4; mt++)
#pragma unroll
                for (int nt = 0; nt < 4; nt++) {
                    mma16816(acc[mt][nt], Af[mt], &Bhf[nt >> 1][(nt & 1) << 1]);
                    mma16816(acc[mt][nt], Af[mt], &Blf[nt >> 1][(nt & 1) << 1]);
                }
        }
        __syncthreads();
    }

    // ---------------- epilogue ----------------
    const int lr = lane >> 2;
    const int lc = (lane & 3) << 1;
#pragma unroll
    for (int mt = 0; mt < 4; mt++) {
#pragma unroll
        for (int h = 0; h < 2; h++) {
            const int row = brow + (wm << 6) + (mt << 4) + lr + (h << 3);
            const size_t crow = (size_t)row * N;
#pragma unroll
            for (int nt = 0; nt < 4; nt++) {
                const int col = bcol + (wn << 5) + (nt << 3) + lc;
                float v0 = acc[mt][nt][2 * h];
                float v1 = acc[mt][nt][2 * h + 1];
                if (mode & 1) {
                    const float2 bb = *(const float2*)&bias[col];
                    v0 += bb.x; v1 += bb.y;
                }
                if (mode & 4) {
                    v0 = 0.5f * v0 * (1.f + erff(v0 * 0.70710678118654752f));
                    v1 = 0.5f * v1 * (1.f + erff(v1 * 0.70710678118654752f));
                }
                if (mode & 2) {
                    const float2 rr = *(const float2*)&Rres[crow + col];
                    v0 += rr.x; v1 += rr.y;
                }
                if (Cf) {
                    float2 o; o.x = v0; o.y = v1;
                    *(float2*)&Cf[crow + col] = o;
                } else {
                    *(__half2*)&Ch[crow + col] = __floats2half2_rn(v0, v1);
                }
            }
        }
    }
}

// ============================================================
// Tensor-core causal flash attention (FA2-style), fp16 in/out.
// qkv: [B*T, 3072] fp16 (q | k | v interleaved by column blocks).
// 4 warps, BQ=64 (16 rows/warp), BK=64, double-buffered K/V.
// 1/sqrt(DH) folded into the exp2 constant.
// ============================================================
#define FSTR 72                        // smem row stride in halves (144 B)
#define LDQKV 3072

__global__ void __launch_bounds__(128) flash_kernel(const __half* __restrict__ qkv,
                                                    __half* __restrict__ at) {
    __shared__ __half Qs[64 * FSTR];
    __shared__ __half Ks[2][64 * FSTR];
    __shared__ __half Vs[2][64 * FSTR];

    const int tid  = threadIdx.x;
    const int lane = tid & 31;
    const int w    = tid >> 5;
    const int lr   = lane >> 2;
    const int lc   = (lane & 3) << 1;
    const int q0   = blockIdx.x << 6;
    const int head = blockIdx.y;
    const int b    = blockIdx.z;
    const size_t base = ((size_t)b * SEQ) * LDQKV + head * DH;
    const float CE = 0.18033688011f;   // log2(e)/8

    const uint32_t qb = smem_u32(Qs);
    const uint32_t kb = smem_u32(Ks);
    const uint32_t vb = smem_u32(Vs);

    // load Q tile (once)
#pragma unroll
    for (int i = 0; i < 4; i++) {
        const int idx = tid + (i << 7);
        const int r = idx >> 3, ch = idx & 7;
        cp16(qb + r * 144 + (ch << 4), qkv + base + (size_t)(q0 + r) * LDQKV + (ch << 3));
    }
    auto load_kv = [&](int kv0, int buf) {
#pragma unroll
        for (int i = 0; i < 4; i++) {
            const int idx = tid + (i << 7);
            const int r = idx >> 3, ch = idx & 7;
            const size_t g = base + (size_t)(kv0 + r) * LDQKV + (ch << 3);
            cp16(kb + buf * (64 * 144) + r * 144 + (ch << 4), qkv + 1024 + g);
            cp16(vb + buf * (64 * 144) + r * 144 + (ch << 4), qkv + 2048 + g);
        }
        asm volatile("cp.async.commit_group;" ::: "memory");
    };

    load_kv(0, 0);
    asm volatile("cp.async.wait_group 0;" ::: "memory");
    __syncthreads();

    float m[2] = {-1e30f, -1e30f}, l[2] = {0.f, 0.f};
    float o[8][4];
#pragma unroll
    for (int j = 0; j < 8; j++)
#pragma unroll
        for (int e = 0; e < 4; e++) o[j][e] = 0.f;

    const int iters = (q0 >> 6) + 1;
    for (int it = 0; it < iters; it++) {
        const int buf = it & 1;
        if (it + 1 < iters) load_kv((it + 1) << 6, buf ^ 1);

        // ---- S = Q K^T ----
        float sacc[8][4];
#pragma unroll
        for (int j = 0; j < 8; j++)
#pragma unroll
            for (int e = 0; e < 4; e++) sacc[j][e] = 0.f;
#pragma unroll
        for (int kk = 0; kk < 4; kk++) {
            uint32_t af[4];
            {
                const int row  = (w << 4) + (lane & 7) + (((lane >> 3) & 1) << 3);
                const int colh = (kk << 4) + ((lane >> 4) << 3);
                ldsm4(af, qb + row * 144 + (colh << 1));
            }
#pragma unroll
            for (int p = 0; p < 4; p++) {
                uint32_t bf[4];
                const int row  = (p << 4) + (lane & 7) + ((lane >= 16) << 3);
                const int colh = (kk << 4) + (((lane >> 3) & 1) << 3);
                ldsm4(bf, kb + buf * (64 * 144) + row * 144 + (colh << 1));
                mma16816(sacc[2 * p],     af, &bf[0]);
                mma16816(sacc[2 * p + 1], af, &bf[2]);
            }
        }

        // ---- causal mask (only the diagonal tile) ----
        const int kv0 = it << 6;
        if (it == iters - 1) {
#pragma unroll
            for (int j = 0; j < 8; j++)
#pragma unroll
                for (int e = 0; e < 4; e++) {
                    const int row = q0 + (w << 4) + lr + ((e >> 1) << 3);
                    const int col = kv0 + (j << 3) + lc + (e & 1);
                    if (col > row) sacc[j][e] = -1e30f;
                }
        }

        // ---- online softmax (rows h=0: lr, h=1: lr+8) ----
#pragma unroll
        for (int h = 0; h < 2; h++) {
            float mx = -1e30f;
#pragma unroll
            for (int j = 0; j < 8; j++)
                mx = fmaxf(mx, fmaxf(sacc[j][2 * h], sacc[j][2 * h + 1]));
            mx = fmaxf(mx, __shfl_xor_sync(0xffffffffu, mx, 1));
            mx = fmaxf(mx, __shfl_xor_sync(0xffffffffu, mx, 2));
            const float mn = fmaxf(m[h], mx);
            const float alpha = ex2((m[h] - mn) * CE);
            m[h] = mn;
            float rs = 0.f;
#pragma unroll
            for (int j = 0; j < 8; j++) {
                sacc[j][2 * h]     = ex2((sacc[j][2 * h]     - mn) * CE);
                sacc[j][2 * h + 1] = ex2((sacc[j][2 * h + 1] - mn) * CE);
                rs += sacc[j][2 * h] + sacc[j][2 * h + 1];
            }
            rs += __shfl_xor_sync(0xffffffffu, rs, 1);
            rs += __shfl_xor_sync(0xffffffffu, rs, 2);
            l[h] = l[h] * alpha + rs;
#pragma unroll
            for (int j = 0; j < 8; j++) {
                o[j][2 * h]     *= alpha;
                o[j][2 * h + 1] *= alpha;
            }
        }

        // ---- O += P V ----
#pragma unroll
        for (int kk = 0; kk < 4; kk++) {
            uint32_t pa[4];
            {
                __half2 t0 = __floats2half2_rn(sacc[2 * kk][0],     sacc[2 * kk][1]);
                __half2 t1 = __floats2half2_rn(sacc[2 * kk][2],     sacc[2 * kk][3]);
                __half2 t2 = __floats2half2_rn(sacc[2 * kk + 1][0], sacc[2 * kk + 1][1]);
                __half2 t3 = __floats2half2_rn(sacc[2 * kk + 1][2], sacc[2 * kk + 1][3]);
                pa[0] = *(uint32_t*)&t0; pa[1] = *(uint32_t*)&t1;
                pa[2] = *(uint32_t*)&t2; pa[3] = *(uint32_t*)&t3;
            }
#pragma unroll
            for (int d = 0; d < 4; d++) {
                uint32_t vf[4];
                const int row  = (kk << 4) + (lane & 15);
                const int colh = (d << 4) + ((lane >> 4) << 3);
                ldsm4t(vf, vb + buf * (64 * 144) + row * 144 + (colh << 1));
                mma16816(o[2 * d],     pa, &vf[0]);
                mma16816(o[2 * d + 1], pa, &vf[2]);
            }
        }

        asm volatile("cp.async.wait_group 0;" ::: "memory");
        __syncthreads();
    }

    // ---- write O / l ----
    const float inv0 = 1.f / l[0], inv1 = 1.f / l[1];
    const size_t obase = ((size_t)b * SEQ) * DM + head * DH;
#pragma unroll
    for (int j = 0; j < 8; j++) {
        const int col = (j << 3) + lc;
        const int r0 = q0 + (w << 4) + lr;
        *(__half2*)&at[obase + (size_t)r0 * DM + col] =
            __floats2half2_rn(o[j][0] * inv0, o[j][1] * inv0);
        *(__half2*)&at[obase + (size_t)(r0 + 8) * DM + col] =
            __floats2half2_rn(o[j][2] * inv1, o[j][3] * inv1);
    }
}

// ============================================================
// launch
// ============================================================
extern "C" void kernel_launch(void* const* d_in, const int* in_sizes, int n_in,
                              void* d_out, int out_size) {
    const float* x    = (const float*)d_in[0];
    const float* wq   = (const float*)d_in[1];
    const float* wk   = (const float*)d_in[2];
    const float* wv   = (const float*)d_in[3];
    const float* wo   = (const float*)d_in[4];
    const float* bo   = (const float*)d_in[5];
    const float* w1   = (const float*)d_in[6];
    const float* b1   = (const float*)d_in[7];
    const float* w2   = (const float*)d_in[8];
    const float* b2   = (const float*)d_in[9];
    const float* ln1s = (const float*)d_in[10];
    const float* ln1b = (const float*)d_in[11];
    const float* ln2s = (const float*)d_in[12];
    const float* ln2b = (const float*)d_in[13];
    float* out = (float*)d_out;

    __half *h, *qkv, *at, *h2, *ff;
    float* x1;
    __half *wqkvh, *wqkvl, *woh, *wol, *w1h, *w1l, *w2h, *w2l;
    cudaGetSymbolAddress((void**)&h,    g_h);
    cudaGetSymbolAddress((void**)&qkv,  g_qkv);
    cudaGetSymbolAddress((void**)&at,   g_at);
    cudaGetSymbolAddress((void**)&x1,   g_x1);
    cudaGetSymbolAddress((void**)&h2,   g_h2);
    cudaGetSymbolAddress((void**)&ff,   g_ff);
    cudaGetSymbolAddress((void**)&wqkvh, g_wqkvh);
    cudaGetSymbolAddress((void**)&wqkvl, g_wqkvl);
    cudaGetSymbolAddress((void**)&woh,  g_woh);  cudaGetSymbolAddress((void**)&wol, g_wol);
    cudaGetSymbolAddress((void**)&w1h,  g_w1h);  cudaGetSymbolAddress((void**)&w1l, g_w1l);
    cudaGetSymbolAddress((void**)&w2h,  g_w2h);  cudaGetSymbolAddress((void**)&w2l, g_w2l);

    const int SMEM = 2 * STAGEB;   // 110592 bytes
    cudaFuncSetAttribute(hgemm_kernel, cudaFuncAttributeMaxDynamicSharedMemorySize, SMEM);

    const dim3 gW1(DM / 32, DM / 32);
    const dim3 gWF1(DFFN / 32, DM / 32);
    const dim3 gWF2(DM / 32, DFFN / 32);

    // weight transpose + split (qkv weights packed into one [3072,1024] buffer)
    wsplit_kernel<<<gW1, 256>>>(wq, wqkvh,               wqkvl,               DM, DM);
    wsplit_kernel<<<gW1, 256>>>(wk, wqkvh + DM * DM,     wqkvl + DM * DM,     DM, DM);
    wsplit_kernel<<<gW1, 256>>>(wv, wqkvh + 2 * DM * DM, wqkvl + 2 * DM * DM, DM, DM);
    wsplit_kernel<<<gW1, 256>>>(wo, woh, wol, DM, DM);
    wsplit_kernel<<<gWF1, 256>>>(w1, w1h, w1l, DM, DFFN);
    wsplit_kernel<<<gWF2, 256>>>(w2, w2h, w2l, DFFN, DM);

    // LN1 -> h (fp16)
    ln_kernel<<<BT, 256>>>(x, ln1s, ln1b, h);

    const dim3 gQKV(3 * DM / 128, BT / 128);   // (24, 32)
    const dim3 gD(DM / 128, BT / 128);         // (8, 32)
    const dim3 gF(DFFN / 128, BT / 128);       // (32, 32)
    const dim3 gAt(SEQ / 64, NH, 2);

    // fused QKV projection (fp16 out)
    hgemm_kernel<<<gQKV, 256, SMEM>>>(h, wqkvh, wqkvl, nullptr, nullptr,
                                      nullptr, qkv, 3 * DM, DM, 0);
    // tensor-core flash attention (fp16 out)
    flash_kernel<<<gAt, 128>>>(qkv, at);
    // out-proj + bias + residual -> x1 (fp32)
    hgemm_kernel<<<gD, 256, SMEM>>>(at, woh, wol, bo, x,
                                    x1, nullptr, DM, DM, 1 | 2);
    // LN2 -> h2 (fp16)
    ln_kernel<<<BT, 256>>>(x1, ln2s, ln2b, h2);
    // FFN1 + bias + GELU -> ff (fp16)
    hgemm_kernel<<<gF, 256, SMEM>>>(h2, w1h, w1l, b1, nullptr,
                                    nullptr, ff, DFFN, DM, 1 | 4);
    // FFN2 + bias + residual -> out (fp32)
    hgemm_kernel<<<gD, 256, SMEM>>>(ff, w2h, w2l, b2, x1,
                                    out, nullptr, DM, DFFN, 1 | 2);
}